// round 4
// baseline (speedup 1.0000x reference)
#include <cuda_runtime.h>
#include <math.h>

#define HIDDEN 128
#define MAXN 50000
#define MAXE 800000

// ---------------- scratch (device globals: no allocation allowed) ----------
__device__ float g_y[(size_t)MAXN * HIDDEN];    // y = A·x  (gathered x)
__device__ float g_s[MAXN];                     // s[i] = sum of edge norms into i
__device__ int   g_degi[MAXN];                  // in-degree (int)
__device__ float g_dinv[MAXN];                  // deg^-1/2
__device__ int   g_off[MAXN + 1];               // CSR row offsets (by dst)
__device__ int   g_cur[MAXN];                   // fill cursors
__device__ int2  g_edge[MAXE];                  // packed (src, norm-bits) per CSR slot
__device__ float g_M2[HIDDEN * HIDDEN];         // M2 = W @ W
__device__ float g_c[HIDDEN];                   // c  = W @ b

// ---------------- degree (int) ----------------------------------------------
__global__ void deg_kernel(const int* __restrict__ dst, int e) {
    int i = blockIdx.x * blockDim.x + threadIdx.x;
    if (i < e) atomicAdd(&g_degi[dst[i]], 1);
}

// ---------------- single-block scan (offsets) + fused deg^-1/2 ---------------
// 1024 threads, each owns a contiguous chunk of ceil(n/1024) nodes.
__global__ void __launch_bounds__(1024)
scan_one_kernel(int n) {
    __shared__ int sh[1024];
    const int t = threadIdx.x;
    const int C = (n + 1023) / 1024;
    const int base = t * C;

    int sum = 0;
    for (int i = 0; i < C; i++) {
        int idx = base + i;
        if (idx < n) sum += g_degi[idx];
    }
    sh[t] = sum;
    __syncthreads();
    for (int d = 1; d < 1024; d <<= 1) {
        int v = (t >= d) ? sh[t - d] : 0;
        __syncthreads();
        sh[t] += v;
        __syncthreads();
    }
    int run = sh[t] - sum;  // exclusive prefix of this thread's chunk
    for (int i = 0; i < C; i++) {
        int idx = base + i;
        if (idx < n) {
            int v = g_degi[idx];
            g_dinv[idx] = rsqrtf((float)v);
            run += v;
            g_off[idx + 1] = run;
        }
    }
    if (t == 0) g_off[0] = 0;
}

// ---------------- CSR fill: slot per edge, packed (src, norm) ---------------
__global__ void fill_kernel(const int* __restrict__ src, const int* __restrict__ dst, int e) {
    int i = blockIdx.x * blockDim.x + threadIdx.x;
    if (i < e) {
        int s = src[i];
        int d = dst[i];
        int pos = g_off[d] + atomicAdd(&g_cur[d], 1);
        int2 ew;
        ew.x = s;
        ew.y = __float_as_int(g_dinv[s] * g_dinv[d]);
        g_edge[pos] = ew;
    }
}

// ---------------- M2 = W @ W and c = W @ b (tiny, side stream) ---------------
// Blocks 0..15: 8 rows of M2 each. Block 16: c.
__global__ void __launch_bounds__(256)
mat_kernel(const float* __restrict__ W, const float* __restrict__ b) {
    if (blockIdx.x == 16) {
        int j = threadIdx.x;
        if (j < HIDDEN) {
            float acc = 0.f;
            for (int k = 0; k < HIDDEN; k++) acc += W[j * HIDDEN + k] * b[k];
            g_c[j] = acc;
        }
        return;
    }
    __shared__ float Wsh[8][HIDDEN];
    const int jbase = blockIdx.x * 8;
    const int tid = threadIdx.x;
    for (int i = tid; i < 8 * HIDDEN; i += 256)
        Wsh[i >> 7][i & 127] = W[(jbase + (i >> 7)) * HIDDEN + (i & 127)];
    __syncthreads();
    const int m = tid & 127;
    const int half = tid >> 7;  // 0 or 1 -> j quads
    float acc[4] = {0.f, 0.f, 0.f, 0.f};
    for (int k = 0; k < HIDDEN; k++) {
        float wk = __ldg(&W[k * HIDDEN + m]);
#pragma unroll
        for (int q = 0; q < 4; q++) acc[q] += Wsh[half * 4 + q][k] * wk;
    }
#pragma unroll
    for (int q = 0; q < 4; q++)
        g_M2[(jbase + half * 4 + q) * HIDDEN + m] = acc[q];
}

// ---------------- gather: y[i] = sum_e norm * x[src],  s[i] = sum_e norm ----
// One warp per dst node; lane owns a float4 column chunk. No atomics.
__global__ void __launch_bounds__(256)
gather_kernel(const float* __restrict__ x, int n) {
    int warp = (blockIdx.x * 256 + threadIdx.x) >> 5;
    int lane = threadIdx.x & 31;
    if (warp >= n) return;
    int p  = g_off[warp];
    int pe = g_off[warp + 1];
    const float4* x4 = reinterpret_cast<const float4*>(x);
    float4 acc = make_float4(0.f, 0.f, 0.f, 0.f);
    float wsum = 0.f;
    for (; p + 3 < pe; p += 4) {
        int2 e0 = __ldg(&g_edge[p]);
        int2 e1 = __ldg(&g_edge[p + 1]);
        int2 e2 = __ldg(&g_edge[p + 2]);
        int2 e3 = __ldg(&g_edge[p + 3]);
        float4 v0 = __ldg(&x4[(size_t)e0.x * 32 + lane]);
        float4 v1 = __ldg(&x4[(size_t)e1.x * 32 + lane]);
        float4 v2 = __ldg(&x4[(size_t)e2.x * 32 + lane]);
        float4 v3 = __ldg(&x4[(size_t)e3.x * 32 + lane]);
        float w0 = __int_as_float(e0.y);
        float w1 = __int_as_float(e1.y);
        float w2 = __int_as_float(e2.y);
        float w3 = __int_as_float(e3.y);
        wsum += w0 + w1 + w2 + w3;
        acc.x += w0 * v0.x + w1 * v1.x + w2 * v2.x + w3 * v3.x;
        acc.y += w0 * v0.y + w1 * v1.y + w2 * v2.y + w3 * v3.y;
        acc.z += w0 * v0.z + w1 * v1.z + w2 * v2.z + w3 * v3.z;
        acc.w += w0 * v0.w + w1 * v1.w + w2 * v2.w + w3 * v3.w;
    }
    for (; p < pe; p++) {
        int2 e0 = __ldg(&g_edge[p]);
        float4 v0 = __ldg(&x4[(size_t)e0.x * 32 + lane]);
        float w0 = __int_as_float(e0.y);
        wsum += w0;
        acc.x += w0 * v0.x; acc.y += w0 * v0.y;
        acc.z += w0 * v0.z; acc.w += w0 * v0.w;
    }
    reinterpret_cast<float4*>(g_y)[(size_t)warp * 32 + lane] = acc;
    if (lane == 0) g_s[warp] = wsum;
}

// ---------------- packed f32x2 helpers ---------------------------------------
__device__ __forceinline__ unsigned long long f32x2_pack(float lo, float hi) {
    unsigned long long r;
    asm("mov.b64 %0, {%1, %2};" : "=l"(r) : "f"(lo), "f"(hi));
    return r;
}
__device__ __forceinline__ void f32x2_fma(unsigned long long& d,
                                          unsigned long long a, unsigned long long b) {
    asm("fma.rn.f32x2 %0, %1, %2, %0;" : "+l"(d) : "l"(a), "l"(b));
}
__device__ __forceinline__ float2 f32x2_unpack(unsigned long long v) {
    float2 r;
    asm("mov.b64 {%0, %1}, %2;" : "=f"(r.x), "=f"(r.y) : "l"(v));
    return r;
}

__device__ __forceinline__ float gelu_exact(float v) {
    return 0.5f * v * (1.0f + erff(v * 0.70710678118654752f));
}

// ---------------- fused GEMM: out = gelu(y @ M2^T + s*c + b) ----------------
// FFMA2: y tile k-major (row pairs load as packed b64), M2 col-padded.
// Thread tile 8 rows (4 packed pairs) x 4 cols.
#define GEMM_ROWS 64
#define WT_STRIDE 132
#define AT_STRIDE 66

__global__ void __launch_bounds__(256, 2)
gemm_fused_kernel(const float* __restrict__ A, const float* __restrict__ M2,
                  const float* __restrict__ cvec, const float* __restrict__ b,
                  const float* __restrict__ svec, float* __restrict__ C, int n) {
    extern __shared__ float smem[];
    float* Wt = smem;                          // [k][j], stride 132
    float* At = smem + HIDDEN * WT_STRIDE;     // [k][r], stride 66

    const int tid  = threadIdx.x;
    const int row0 = blockIdx.x * GEMM_ROWS;

    for (int i = tid; i < HIDDEN * HIDDEN; i += 256) {
        int j = i >> 7;
        int k = i & 127;
        Wt[k * WT_STRIDE + j] = M2[i];
    }
    const float4* A4 = reinterpret_cast<const float4*>(A);
    for (int i = tid; i < GEMM_ROWS * 32; i += 256) {
        int r  = i >> 5;
        int c4 = i & 31;
        int gr = row0 + r;
        float4 v = (gr < n) ? A4[(size_t)gr * 32 + c4] : make_float4(0.f, 0.f, 0.f, 0.f);
        At[(4 * c4 + 0) * AT_STRIDE + r] = v.x;
        At[(4 * c4 + 1) * AT_STRIDE + r] = v.y;
        At[(4 * c4 + 2) * AT_STRIDE + r] = v.z;
        At[(4 * c4 + 3) * AT_STRIDE + r] = v.w;
    }
    __syncthreads();

    const int tx = tid & 31;
    const int ty = tid >> 5;

    unsigned long long acc[4][4];
#pragma unroll
    for (int p = 0; p < 4; p++)
#pragma unroll
        for (int c = 0; c < 4; c++) acc[p][c] = 0ull;

    const float* at_base = &At[ty * 8];
    const float* wt_base = &Wt[tx * 4];

#pragma unroll 4
    for (int k = 0; k < HIDDEN; k++) {
        float4 w = *reinterpret_cast<const float4*>(&wt_base[k * WT_STRIDE]);
        unsigned long long w0 = f32x2_pack(w.x, w.x);
        unsigned long long w1 = f32x2_pack(w.y, w.y);
        unsigned long long w2 = f32x2_pack(w.z, w.z);
        unsigned long long w3 = f32x2_pack(w.w, w.w);
        const float* ak = &at_base[k * AT_STRIDE];
        unsigned long long a0 = *reinterpret_cast<const unsigned long long*>(ak + 0);
        unsigned long long a1 = *reinterpret_cast<const unsigned long long*>(ak + 2);
        unsigned long long a2 = *reinterpret_cast<const unsigned long long*>(ak + 4);
        unsigned long long a3 = *reinterpret_cast<const unsigned long long*>(ak + 6);
        f32x2_fma(acc[0][0], a0, w0); f32x2_fma(acc[0][1], a0, w1);
        f32x2_fma(acc[0][2], a0, w2); f32x2_fma(acc[0][3], a0, w3);
        f32x2_fma(acc[1][0], a1, w0); f32x2_fma(acc[1][1], a1, w1);
        f32x2_fma(acc[1][2], a1, w2); f32x2_fma(acc[1][3], a1, w3);
        f32x2_fma(acc[2][0], a2, w0); f32x2_fma(acc[2][1], a2, w1);
        f32x2_fma(acc[2][2], a2, w2); f32x2_fma(acc[2][3], a2, w3);
        f32x2_fma(acc[3][0], a3, w0); f32x2_fma(acc[3][1], a3, w1);
        f32x2_fma(acc[3][2], a3, w2); f32x2_fma(acc[3][3], a3, w3);
    }

    float4 bv = reinterpret_cast<const float4*>(b)[tx];
    float4 cv = reinterpret_cast<const float4*>(cvec)[tx];
#pragma unroll
    for (int p = 0; p < 4; p++) {
        int r0 = row0 + ty * 8 + 2 * p;
        float2 c0 = f32x2_unpack(acc[p][0]);
        float2 c1 = f32x2_unpack(acc[p][1]);
        float2 c2 = f32x2_unpack(acc[p][2]);
        float2 c3 = f32x2_unpack(acc[p][3]);
        float s0 = (r0 < n) ? svec[r0] : 0.f;
        float s1 = (r0 + 1 < n) ? svec[r0 + 1] : 0.f;
        float4 o0 = make_float4(c0.x + s0 * cv.x + bv.x, c1.x + s0 * cv.y + bv.y,
                                c2.x + s0 * cv.z + bv.z, c3.x + s0 * cv.w + bv.w);
        float4 o1 = make_float4(c0.y + s1 * cv.x + bv.x, c1.y + s1 * cv.y + bv.y,
                                c2.y + s1 * cv.z + bv.z, c3.y + s1 * cv.w + bv.w);
        o0.x = gelu_exact(o0.x); o0.y = gelu_exact(o0.y);
        o0.z = gelu_exact(o0.z); o0.w = gelu_exact(o0.w);
        o1.x = gelu_exact(o1.x); o1.y = gelu_exact(o1.y);
        o1.z = gelu_exact(o1.z); o1.w = gelu_exact(o1.w);
        if (r0 < n)
            *reinterpret_cast<float4*>(&C[(size_t)r0 * HIDDEN + tx * 4]) = o0;
        if (r0 + 1 < n)
            *reinterpret_cast<float4*>(&C[(size_t)(r0 + 1) * HIDDEN + tx * 4]) = o1;
    }
}

// ---------------- launch -----------------------------------------------------
extern "C" void kernel_launch(void* const* d_in, const int* in_sizes, int n_in,
                              void* d_out, int out_size) {
    const float* x = (const float*)d_in[0];
    const float* W = (const float*)d_in[1];
    const float* b = (const float*)d_in[2];
    const int* ei  = (const int*)d_in[3];

    const int n = in_sizes[0] / HIDDEN;   // 50000
    const int e = in_sizes[3] / 2;        // 800000
    const int* src = ei;
    const int* dst = ei + e;

    float* out = (float*)d_out;

    static float* p_y   = nullptr;
    static float* p_s   = nullptr;
    static float* p_M2  = nullptr;
    static float* p_c   = nullptr;
    static int*   p_deg = nullptr;
    static int*   p_cur = nullptr;
    static cudaStream_t s2 = nullptr;
    static cudaEvent_t ev_fork = nullptr, ev_join = nullptr;
    if (!p_y) {
        cudaGetSymbolAddress((void**)&p_y, g_y);
        cudaGetSymbolAddress((void**)&p_s, g_s);
        cudaGetSymbolAddress((void**)&p_M2, g_M2);
        cudaGetSymbolAddress((void**)&p_c, g_c);
        cudaGetSymbolAddress((void**)&p_deg, g_degi);
        cudaGetSymbolAddress((void**)&p_cur, g_cur);
        cudaStreamCreateWithFlags(&s2, cudaStreamNonBlocking);
        cudaEventCreateWithFlags(&ev_fork, cudaEventDisableTiming);
        cudaEventCreateWithFlags(&ev_join, cudaEventDisableTiming);
    }

    const size_t smem_bytes = (HIDDEN * WT_STRIDE + HIDDEN * AT_STRIDE) * sizeof(float);
    cudaFuncSetAttribute(gemm_fused_kernel,
                         cudaFuncAttributeMaxDynamicSharedMemorySize, (int)smem_bytes);

    // ---- fork: M2 = W@W, c = W@b on side stream (hidden under CSR chain) ---
    cudaEventRecord(ev_fork, 0);
    cudaStreamWaitEvent(s2, ev_fork, 0);
    mat_kernel<<<17, 256, 0, s2>>>(W, b);
    cudaEventRecord(ev_join, s2);

    // ---- CSR build chain on main stream ------------------------------------
    cudaMemsetAsync(p_deg, 0, (size_t)n * sizeof(int));
    cudaMemsetAsync(p_cur, 0, (size_t)n * sizeof(int));
    deg_kernel<<<(e + 255) / 256, 256>>>(dst, e);
    scan_one_kernel<<<1, 1024>>>(n);            // offsets + deg^-1/2, 1 launch
    fill_kernel<<<(e + 255) / 256, 256>>>(src, dst, e);

    // ---- gather on x: y = A·x, s = A·1 --------------------------------------
    unsigned gthreads = (unsigned)n * 32u;
    gather_kernel<<<(gthreads + 255) / 256, 256>>>(x, n);

    // ---- join: fused GEMM needs M2, c ---------------------------------------
    cudaStreamWaitEvent(0, ev_join, 0);
    const int gemm_blocks = (n + GEMM_ROWS - 1) / GEMM_ROWS;
    gemm_fused_kernel<<<gemm_blocks, 256, smem_bytes>>>(p_y, p_M2, p_c, b, p_s, out, n);
}

// round 5
// speedup vs baseline: 1.0526x; 1.0526x over previous
#include <cuda_runtime.h>
#include <cuda_fp16.h>
#include <math.h>

#define HIDDEN 128
#define MAXN 50000
#define MAXE 800000

// ---------------- scratch (device globals: no allocation allowed) ----------
__device__ float  g_y[(size_t)MAXN * HIDDEN];   // y = A·x  (gathered x)
__device__ __half g_xh[(size_t)MAXN * HIDDEN];  // fp16 copy of x
__device__ float  g_s[MAXN];                    // s[i] = sum of edge norms into i
__device__ int    g_degi[MAXN];                 // in-degree (int)
__device__ float  g_dinv[MAXN];                 // deg^-1/2
__device__ int    g_off[MAXN];                  // CSR starts; after fill = ends
__device__ int2   g_edge[MAXE];                 // packed (src, norm-bits) per CSR slot
__device__ float  g_M2[HIDDEN * HIDDEN];        // M2 = W @ W
__device__ float  g_c[HIDDEN];                  // c  = W @ b

// ---------------- degree (int) ----------------------------------------------
__global__ void deg_kernel(const int* __restrict__ dst, int e) {
    int i = blockIdx.x * blockDim.x + threadIdx.x;
    if (i < e) atomicAdd(&g_degi[dst[i]], 1);
}

// ---------------- x -> fp16 (side stream) ------------------------------------
__global__ void __launch_bounds__(256)
cvt_kernel(const float* __restrict__ x, int total4) {
    int i = blockIdx.x * 256 + threadIdx.x;
    if (i < total4) {
        float4 v = reinterpret_cast<const float4*>(x)[i];
        __half2 a = __floats2half2_rn(v.x, v.y);
        __half2 b = __floats2half2_rn(v.z, v.w);
        uint2 o;
        o.x = *reinterpret_cast<unsigned*>(&a);
        o.y = *reinterpret_cast<unsigned*>(&b);
        reinterpret_cast<uint2*>(g_xh)[i] = o;
    }
}

// ---------------- single-block scan (starts) + fused deg^-1/2 ----------------
// 1024 threads, each owns a contiguous chunk of ceil(n/1024) nodes.
// Writes g_off[i] = exclusive prefix (start of row i).
__global__ void __launch_bounds__(1024)
scan_one_kernel(int n) {
    __shared__ int sh[1024];
    const int t = threadIdx.x;
    const int C = (n + 1023) / 1024;
    const int base = t * C;

    int sum = 0;
    for (int i = 0; i < C; i++) {
        int idx = base + i;
        if (idx < n) sum += g_degi[idx];
    }
    sh[t] = sum;
    __syncthreads();
    for (int d = 1; d < 1024; d <<= 1) {
        int v = (t >= d) ? sh[t - d] : 0;
        __syncthreads();
        sh[t] += v;
        __syncthreads();
    }
    int run = sh[t] - sum;  // exclusive prefix at chunk start
    for (int i = 0; i < C; i++) {
        int idx = base + i;
        if (idx < n) {
            int v = g_degi[idx];
            g_dinv[idx] = rsqrtf((float)v);
            g_off[idx] = run;   // start of row idx
            run += v;
        }
    }
}

// ---------------- CSR fill: cursor-free (mutates starts -> ends) -------------
__global__ void fill_kernel(const int* __restrict__ src, const int* __restrict__ dst, int e) {
    int i = blockIdx.x * blockDim.x + threadIdx.x;
    if (i < e) {
        int s = src[i];
        int d = dst[i];
        int pos = atomicAdd(&g_off[d], 1);
        int2 ew;
        ew.x = s;
        ew.y = __float_as_int(g_dinv[s] * g_dinv[d]);
        g_edge[pos] = ew;
    }
}

// ---------------- M2 = W @ W and c = W @ b (tiny, side stream) ---------------
__global__ void __launch_bounds__(256)
mat_kernel(const float* __restrict__ W, const float* __restrict__ b) {
    if (blockIdx.x == 16) {
        int j = threadIdx.x;
        if (j < HIDDEN) {
            float acc = 0.f;
            for (int k = 0; k < HIDDEN; k++) acc += W[j * HIDDEN + k] * b[k];
            g_c[j] = acc;
        }
        return;
    }
    __shared__ float Wsh[8][HIDDEN];
    const int jbase = blockIdx.x * 8;
    const int tid = threadIdx.x;
    for (int i = tid; i < 8 * HIDDEN; i += 256)
        Wsh[i >> 7][i & 127] = W[(jbase + (i >> 7)) * HIDDEN + (i & 127)];
    __syncthreads();
    const int m = tid & 127;
    const int half = tid >> 7;
    float acc[4] = {0.f, 0.f, 0.f, 0.f};
    for (int k = 0; k < HIDDEN; k++) {
        float wk = __ldg(&W[k * HIDDEN + m]);
#pragma unroll
        for (int q = 0; q < 4; q++) acc[q] += Wsh[half * 4 + q][k] * wk;
    }
#pragma unroll
    for (int q = 0; q < 4; q++)
        g_M2[(jbase + half * 4 + q) * HIDDEN + m] = acc[q];
}

// ---------------- gather (fp16 src): y[i] = sum norm*x[src], s[i] = sum norm -
// One warp per dst node; lane owns 4 columns (one 8B load per edge).
__global__ void __launch_bounds__(256)
gather_kernel(int n) {
    int warp = (blockIdx.x * 256 + threadIdx.x) >> 5;
    int lane = threadIdx.x & 31;
    if (warp >= n) return;
    // after fill: g_off[i] = end of row i; start = end of row i-1 (0 for i=0)
    int p  = (warp == 0) ? 0 : __ldg(&g_off[warp - 1]);
    int pe = __ldg(&g_off[warp]);
    const uint2* x2 = reinterpret_cast<const uint2*>(g_xh);
    float4 acc = make_float4(0.f, 0.f, 0.f, 0.f);
    float wsum = 0.f;
#pragma unroll 1
    for (; p + 3 < pe; p += 4) {
        int2 e0 = __ldg(&g_edge[p]);
        int2 e1 = __ldg(&g_edge[p + 1]);
        int2 e2 = __ldg(&g_edge[p + 2]);
        int2 e3 = __ldg(&g_edge[p + 3]);
        uint2 u0 = __ldg(&x2[(size_t)e0.x * 32 + lane]);
        uint2 u1 = __ldg(&x2[(size_t)e1.x * 32 + lane]);
        uint2 u2 = __ldg(&x2[(size_t)e2.x * 32 + lane]);
        uint2 u3 = __ldg(&x2[(size_t)e3.x * 32 + lane]);
        float w0 = __int_as_float(e0.y);
        float w1 = __int_as_float(e1.y);
        float w2 = __int_as_float(e2.y);
        float w3 = __int_as_float(e3.y);
        wsum += w0 + w1 + w2 + w3;
        float2 a0 = __half22float2(*reinterpret_cast<__half2*>(&u0.x));
        float2 b0 = __half22float2(*reinterpret_cast<__half2*>(&u0.y));
        float2 a1 = __half22float2(*reinterpret_cast<__half2*>(&u1.x));
        float2 b1 = __half22float2(*reinterpret_cast<__half2*>(&u1.y));
        float2 a2 = __half22float2(*reinterpret_cast<__half2*>(&u2.x));
        float2 b2 = __half22float2(*reinterpret_cast<__half2*>(&u2.y));
        float2 a3 = __half22float2(*reinterpret_cast<__half2*>(&u3.x));
        float2 b3 = __half22float2(*reinterpret_cast<__half2*>(&u3.y));
        acc.x += w0 * a0.x + w1 * a1.x + w2 * a2.x + w3 * a3.x;
        acc.y += w0 * a0.y + w1 * a1.y + w2 * a2.y + w3 * a3.y;
        acc.z += w0 * b0.x + w1 * b1.x + w2 * b2.x + w3 * b3.x;
        acc.w += w0 * b0.y + w1 * b1.y + w2 * b2.y + w3 * b3.y;
    }
    for (; p < pe; p++) {
        int2 e0 = __ldg(&g_edge[p]);
        uint2 u0 = __ldg(&x2[(size_t)e0.x * 32 + lane]);
        float w0 = __int_as_float(e0.y);
        wsum += w0;
        float2 a0 = __half22float2(*reinterpret_cast<__half2*>(&u0.x));
        float2 b0 = __half22float2(*reinterpret_cast<__half2*>(&u0.y));
        acc.x += w0 * a0.x; acc.y += w0 * a0.y;
        acc.z += w0 * b0.x; acc.w += w0 * b0.y;
    }
    reinterpret_cast<float4*>(g_y)[(size_t)warp * 32 + lane] = acc;
    if (lane == 0) g_s[warp] = wsum;
}

// ---------------- packed f32x2 helpers ---------------------------------------
__device__ __forceinline__ unsigned long long f32x2_pack(float lo, float hi) {
    unsigned long long r;
    asm("mov.b64 %0, {%1, %2};" : "=l"(r) : "f"(lo), "f"(hi));
    return r;
}
__device__ __forceinline__ void f32x2_fma(unsigned long long& d,
                                          unsigned long long a, unsigned long long b) {
    asm("fma.rn.f32x2 %0, %1, %2, %0;" : "+l"(d) : "l"(a), "l"(b));
}
__device__ __forceinline__ float2 f32x2_unpack(unsigned long long v) {
    float2 r;
    asm("mov.b64 {%0, %1}, %2;" : "=f"(r.x), "=f"(r.y) : "l"(v));
    return r;
}

__device__ __forceinline__ float gelu_exact(float v) {
    return 0.5f * v * (1.0f + erff(v * 0.70710678118654752f));
}

// ---------------- fused GEMM: out = gelu(y @ M2^T + s*c + b) ----------------
#define GEMM_ROWS 64
#define WT_STRIDE 132
#define AT_STRIDE 66

__global__ void __launch_bounds__(256, 2)
gemm_fused_kernel(const float* __restrict__ A, const float* __restrict__ M2,
                  const float* __restrict__ cvec, const float* __restrict__ b,
                  const float* __restrict__ svec, float* __restrict__ C, int n) {
    extern __shared__ float smem[];
    float* Wt = smem;                          // [k][j], stride 132
    float* At = smem + HIDDEN * WT_STRIDE;     // [k][r], stride 66

    const int tid  = threadIdx.x;
    const int row0 = blockIdx.x * GEMM_ROWS;

    for (int i = tid; i < HIDDEN * HIDDEN; i += 256) {
        int j = i >> 7;
        int k = i & 127;
        Wt[k * WT_STRIDE + j] = M2[i];
    }
    const float4* A4 = reinterpret_cast<const float4*>(A);
    for (int i = tid; i < GEMM_ROWS * 32; i += 256) {
        int r  = i >> 5;
        int c4 = i & 31;
        int gr = row0 + r;
        float4 v = (gr < n) ? A4[(size_t)gr * 32 + c4] : make_float4(0.f, 0.f, 0.f, 0.f);
        At[(4 * c4 + 0) * AT_STRIDE + r] = v.x;
        At[(4 * c4 + 1) * AT_STRIDE + r] = v.y;
        At[(4 * c4 + 2) * AT_STRIDE + r] = v.z;
        At[(4 * c4 + 3) * AT_STRIDE + r] = v.w;
    }
    __syncthreads();

    const int tx = tid & 31;
    const int ty = tid >> 5;

    unsigned long long acc[4][4];
#pragma unroll
    for (int p = 0; p < 4; p++)
#pragma unroll
        for (int c = 0; c < 4; c++) acc[p][c] = 0ull;

    const float* at_base = &At[ty * 8];
    const float* wt_base = &Wt[tx * 4];

#pragma unroll 4
    for (int k = 0; k < HIDDEN; k++) {
        float4 w = *reinterpret_cast<const float4*>(&wt_base[k * WT_STRIDE]);
        unsigned long long w0 = f32x2_pack(w.x, w.x);
        unsigned long long w1 = f32x2_pack(w.y, w.y);
        unsigned long long w2 = f32x2_pack(w.z, w.z);
        unsigned long long w3 = f32x2_pack(w.w, w.w);
        const float* ak = &at_base[k * AT_STRIDE];
        unsigned long long a0 = *reinterpret_cast<const unsigned long long*>(ak + 0);
        unsigned long long a1 = *reinterpret_cast<const unsigned long long*>(ak + 2);
        unsigned long long a2 = *reinterpret_cast<const unsigned long long*>(ak + 4);
        unsigned long long a3 = *reinterpret_cast<const unsigned long long*>(ak + 6);
        f32x2_fma(acc[0][0], a0, w0); f32x2_fma(acc[0][1], a0, w1);
        f32x2_fma(acc[0][2], a0, w2); f32x2_fma(acc[0][3], a0, w3);
        f32x2_fma(acc[1][0], a1, w0); f32x2_fma(acc[1][1], a1, w1);
        f32x2_fma(acc[1][2], a1, w2); f32x2_fma(acc[1][3], a1, w3);
        f32x2_fma(acc[2][0], a2, w0); f32x2_fma(acc[2][1], a2, w1);
        f32x2_fma(acc[2][2], a2, w2); f32x2_fma(acc[2][3], a2, w3);
        f32x2_fma(acc[3][0], a3, w0); f32x2_fma(acc[3][1], a3, w1);
        f32x2_fma(acc[3][2], a3, w2); f32x2_fma(acc[3][3], a3, w3);
    }

    float4 bv = reinterpret_cast<const float4*>(b)[tx];
    float4 cv = reinterpret_cast<const float4*>(cvec)[tx];
#pragma unroll
    for (int p = 0; p < 4; p++) {
        int r0 = row0 + ty * 8 + 2 * p;
        float2 c0 = f32x2_unpack(acc[p][0]);
        float2 c1 = f32x2_unpack(acc[p][1]);
        float2 c2 = f32x2_unpack(acc[p][2]);
        float2 c3 = f32x2_unpack(acc[p][3]);
        float s0 = (r0 < n) ? svec[r0] : 0.f;
        float s1 = (r0 + 1 < n) ? svec[r0 + 1] : 0.f;
        float4 o0 = make_float4(c0.x + s0 * cv.x + bv.x, c1.x + s0 * cv.y + bv.y,
                                c2.x + s0 * cv.z + bv.z, c3.x + s0 * cv.w + bv.w);
        float4 o1 = make_float4(c0.y + s1 * cv.x + bv.x, c1.y + s1 * cv.y + bv.y,
                                c2.y + s1 * cv.z + bv.z, c3.y + s1 * cv.w + bv.w);
        o0.x = gelu_exact(o0.x); o0.y = gelu_exact(o0.y);
        o0.z = gelu_exact(o0.z); o0.w = gelu_exact(o0.w);
        o1.x = gelu_exact(o1.x); o1.y = gelu_exact(o1.y);
        o1.z = gelu_exact(o1.z); o1.w = gelu_exact(o1.w);
        if (r0 < n)
            *reinterpret_cast<float4*>(&C[(size_t)r0 * HIDDEN + tx * 4]) = o0;
        if (r0 + 1 < n)
            *reinterpret_cast<float4*>(&C[(size_t)(r0 + 1) * HIDDEN + tx * 4]) = o1;
    }
}

// ---------------- launch -----------------------------------------------------
extern "C" void kernel_launch(void* const* d_in, const int* in_sizes, int n_in,
                              void* d_out, int out_size) {
    const float* x = (const float*)d_in[0];
    const float* W = (const float*)d_in[1];
    const float* b = (const float*)d_in[2];
    const int* ei  = (const int*)d_in[3];

    const int n = in_sizes[0] / HIDDEN;   // 50000
    const int e = in_sizes[3] / 2;        // 800000
    const int* src = ei;
    const int* dst = ei + e;

    float* out = (float*)d_out;

    static float* p_y   = nullptr;
    static float* p_s   = nullptr;
    static float* p_M2  = nullptr;
    static float* p_c   = nullptr;
    static int*   p_deg = nullptr;
    static cudaStream_t s2 = nullptr;
    static cudaEvent_t ev_fork = nullptr, ev_join = nullptr;
    if (!p_y) {
        cudaGetSymbolAddress((void**)&p_y, g_y);
        cudaGetSymbolAddress((void**)&p_s, g_s);
        cudaGetSymbolAddress((void**)&p_M2, g_M2);
        cudaGetSymbolAddress((void**)&p_c, g_c);
        cudaGetSymbolAddress((void**)&p_deg, g_degi);
        cudaStreamCreateWithFlags(&s2, cudaStreamNonBlocking);
        cudaEventCreateWithFlags(&ev_fork, cudaEventDisableTiming);
        cudaEventCreateWithFlags(&ev_join, cudaEventDisableTiming);
    }

    const size_t smem_bytes = (HIDDEN * WT_STRIDE + HIDDEN * AT_STRIDE) * sizeof(float);
    cudaFuncSetAttribute(gemm_fused_kernel,
                         cudaFuncAttributeMaxDynamicSharedMemorySize, (int)smem_bytes);

    // ---- fork: x->fp16 convert + (M2, c) on side stream --------------------
    cudaEventRecord(ev_fork, 0);
    cudaStreamWaitEvent(s2, ev_fork, 0);
    int total4 = n * 32;  // float4 count
    cvt_kernel<<<(total4 + 255) / 256, 256, 0, s2>>>(x, total4);
    mat_kernel<<<17, 256, 0, s2>>>(W, b);
    cudaEventRecord(ev_join, s2);

    // ---- CSR build chain on main stream ------------------------------------
    cudaMemsetAsync(p_deg, 0, (size_t)n * sizeof(int));
    deg_kernel<<<(e + 255) / 256, 256>>>(dst, e);
    scan_one_kernel<<<1, 1024>>>(n);            // starts + deg^-1/2, 1 launch
    fill_kernel<<<(e + 255) / 256, 256>>>(src, dst, e);

    // ---- join: gather needs fp16 x; fused GEMM needs M2, c ------------------
    cudaStreamWaitEvent(0, ev_join, 0);
    unsigned gthreads = (unsigned)n * 32u;
    gather_kernel<<<(gthreads + 255) / 256, 256>>>(n);

    const int gemm_blocks = (n + GEMM_ROWS - 1) / GEMM_ROWS;
    gemm_fused_kernel<<<gemm_blocks, 256, smem_bytes>>>(p_y, p_M2, p_c, b, p_s, out, n);
}

// round 6
// speedup vs baseline: 1.6257x; 1.5445x over previous
#include <cuda_runtime.h>
#include <cuda_fp16.h>
#include <math.h>

#define HIDDEN 128
#define MAXN 50000
#define MAXE 800000

// ---------------- scratch (device globals: no allocation allowed) ----------
__device__ float  g_y[(size_t)MAXN * HIDDEN];   // y = A·x  (gathered x)
__device__ __half g_xh[(size_t)MAXN * HIDDEN];  // fp16 copy of x
__device__ float  g_s[MAXN];                    // s[i] = sum of edge norms into i
__device__ int    g_degi[MAXN];                 // in-degree (int)
__device__ float  g_dinv[MAXN];                 // deg^-1/2
__device__ int    g_off[MAXN];                  // CSR starts; after fill = ends
__device__ int2   g_edge[MAXE];                 // packed (src, norm-bits) per CSR slot
__device__ float  g_M2[HIDDEN * HIDDEN];        // M2 = W @ W
__device__ float  g_c[HIDDEN];                  // c  = W @ b
__device__ int    g_bsum[64];                   // block sums for scan

// ---------------- degree (int) ----------------------------------------------
__global__ void deg_kernel(const int* __restrict__ dst, int e) {
    int i = blockIdx.x * blockDim.x + threadIdx.x;
    if (i < e) atomicAdd(&g_degi[dst[i]], 1);
}

// ---------------- x -> fp16 (side stream) ------------------------------------
__global__ void __launch_bounds__(256)
cvt_kernel(const float* __restrict__ x, int total4) {
    int i = blockIdx.x * 256 + threadIdx.x;
    if (i < total4) {
        float4 v = reinterpret_cast<const float4*>(x)[i];
        __half2 a = __floats2half2_rn(v.x, v.y);
        __half2 b = __floats2half2_rn(v.z, v.w);
        uint2 o;
        o.x = *reinterpret_cast<unsigned*>(&a);
        o.y = *reinterpret_cast<unsigned*>(&b);
        reinterpret_cast<uint2*>(g_xh)[i] = o;
    }
}

// ---------------- 3-kernel scan -> exclusive starts (+ fused deg^-1/2) -------
__global__ void __launch_bounds__(1024)
scan_block_kernel(int n) {
    __shared__ int sh[1024];
    int t = threadIdx.x;
    int i = blockIdx.x * 1024 + t;
    int v = (i < n) ? g_degi[i] : 0;
    if (i < n) g_dinv[i] = rsqrtf((float)v);
    sh[t] = v;
    __syncthreads();
    for (int d = 1; d < 1024; d <<= 1) {
        int u = (t >= d) ? sh[t - d] : 0;
        __syncthreads();
        sh[t] += u;
        __syncthreads();
    }
    if (i < n) g_off[i] = sh[t] - v;           // exclusive within block
    if (t == 1023) g_bsum[blockIdx.x] = sh[1023];
}

__global__ void scan_sums_kernel(int nb) {
    __shared__ int sh[64];
    int t = threadIdx.x;
    sh[t] = (t < nb) ? g_bsum[t] : 0;
    __syncthreads();
    for (int d = 1; d < 64; d <<= 1) {
        int u = (t >= d) ? sh[t - d] : 0;
        __syncthreads();
        sh[t] += u;
        __syncthreads();
    }
    if (t < nb) g_bsum[t] = sh[t];             // inclusive block prefix
}

__global__ void scan_add_kernel(int n) {
    int i = blockIdx.x * blockDim.x + threadIdx.x;
    if (i < n) {
        int blk = i >> 10;
        if (blk > 0) g_off[i] += g_bsum[blk - 1];
    }
}

// ---------------- CSR fill: cursor-free (mutates starts -> ends) -------------
__global__ void fill_kernel(const int* __restrict__ src, const int* __restrict__ dst, int e) {
    int i = blockIdx.x * blockDim.x + threadIdx.x;
    if (i < e) {
        int s = src[i];
        int d = dst[i];
        int pos = atomicAdd(&g_off[d], 1);
        int2 ew;
        ew.x = s;
        ew.y = __float_as_int(g_dinv[s] * g_dinv[d]);
        g_edge[pos] = ew;
    }
}

// ---------------- M2 = W @ W and c = W @ b (tiny, side stream) ---------------
__global__ void __launch_bounds__(256)
mat_kernel(const float* __restrict__ W, const float* __restrict__ b) {
    if (blockIdx.x == 16) {
        int j = threadIdx.x;
        if (j < HIDDEN) {
            float acc = 0.f;
            for (int k = 0; k < HIDDEN; k++) acc += W[j * HIDDEN + k] * b[k];
            g_c[j] = acc;
        }
        return;
    }
    __shared__ float Wsh[8][HIDDEN];
    const int jbase = blockIdx.x * 8;
    const int tid = threadIdx.x;
    for (int i = tid; i < 8 * HIDDEN; i += 256)
        Wsh[i >> 7][i & 127] = W[(jbase + (i >> 7)) * HIDDEN + (i & 127)];
    __syncthreads();
    const int m = tid & 127;
    const int half = tid >> 7;
    float acc[4] = {0.f, 0.f, 0.f, 0.f};
    for (int k = 0; k < HIDDEN; k++) {
        float wk = __ldg(&W[k * HIDDEN + m]);
#pragma unroll
        for (int q = 0; q < 4; q++) acc[q] += Wsh[half * 4 + q][k] * wk;
    }
#pragma unroll
    for (int q = 0; q < 4; q++)
        g_M2[(jbase + half * 4 + q) * HIDDEN + m] = acc[q];
}

// ---------------- gather (fp16 src): y[i] = sum norm*x[src], s[i] = sum norm -
__global__ void __launch_bounds__(256)
gather_kernel(int n) {
    int warp = (blockIdx.x * 256 + threadIdx.x) >> 5;
    int lane = threadIdx.x & 31;
    if (warp >= n) return;
    // after fill: g_off[i] = end of row i; start = end of row i-1 (0 for i=0)
    int p  = (warp == 0) ? 0 : __ldg(&g_off[warp - 1]);
    int pe = __ldg(&g_off[warp]);
    const uint2* x2 = reinterpret_cast<const uint2*>(g_xh);
    float4 acc = make_float4(0.f, 0.f, 0.f, 0.f);
    float wsum = 0.f;
#pragma unroll 1
    for (; p + 3 < pe; p += 4) {
        int2 e0 = __ldg(&g_edge[p]);
        int2 e1 = __ldg(&g_edge[p + 1]);
        int2 e2 = __ldg(&g_edge[p + 2]);
        int2 e3 = __ldg(&g_edge[p + 3]);
        uint2 u0 = __ldg(&x2[(size_t)e0.x * 32 + lane]);
        uint2 u1 = __ldg(&x2[(size_t)e1.x * 32 + lane]);
        uint2 u2 = __ldg(&x2[(size_t)e2.x * 32 + lane]);
        uint2 u3 = __ldg(&x2[(size_t)e3.x * 32 + lane]);
        float w0 = __int_as_float(e0.y);
        float w1 = __int_as_float(e1.y);
        float w2 = __int_as_float(e2.y);
        float w3 = __int_as_float(e3.y);
        wsum += w0 + w1 + w2 + w3;
        float2 a0 = __half22float2(*reinterpret_cast<__half2*>(&u0.x));
        float2 b0 = __half22float2(*reinterpret_cast<__half2*>(&u0.y));
        float2 a1 = __half22float2(*reinterpret_cast<__half2*>(&u1.x));
        float2 b1 = __half22float2(*reinterpret_cast<__half2*>(&u1.y));
        float2 a2 = __half22float2(*reinterpret_cast<__half2*>(&u2.x));
        float2 b2 = __half22float2(*reinterpret_cast<__half2*>(&u2.y));
        float2 a3 = __half22float2(*reinterpret_cast<__half2*>(&u3.x));
        float2 b3 = __half22float2(*reinterpret_cast<__half2*>(&u3.y));
        acc.x += w0 * a0.x + w1 * a1.x + w2 * a2.x + w3 * a3.x;
        acc.y += w0 * a0.y + w1 * a1.y + w2 * a2.y + w3 * a3.y;
        acc.z += w0 * b0.x + w1 * b1.x + w2 * b2.x + w3 * b3.x;
        acc.w += w0 * b0.y + w1 * b1.y + w2 * b2.y + w3 * b3.y;
    }
    for (; p < pe; p++) {
        int2 e0 = __ldg(&g_edge[p]);
        uint2 u0 = __ldg(&x2[(size_t)e0.x * 32 + lane]);
        float w0 = __int_as_float(e0.y);
        wsum += w0;
        float2 a0 = __half22float2(*reinterpret_cast<__half2*>(&u0.x));
        float2 b0 = __half22float2(*reinterpret_cast<__half2*>(&u0.y));
        acc.x += w0 * a0.x; acc.y += w0 * a0.y;
        acc.z += w0 * b0.x; acc.w += w0 * b0.y;
    }
    reinterpret_cast<float4*>(g_y)[(size_t)warp * 32 + lane] = acc;
    if (lane == 0) g_s[warp] = wsum;
}

// ---------------- packed f32x2 helpers ---------------------------------------
__device__ __forceinline__ unsigned long long f32x2_pack(float lo, float hi) {
    unsigned long long r;
    asm("mov.b64 %0, {%1, %2};" : "=l"(r) : "f"(lo), "f"(hi));
    return r;
}
__device__ __forceinline__ void f32x2_fma(unsigned long long& d,
                                          unsigned long long a, unsigned long long b) {
    asm("fma.rn.f32x2 %0, %1, %2, %0;" : "+l"(d) : "l"(a), "l"(b));
}
__device__ __forceinline__ float2 f32x2_unpack(unsigned long long v) {
    float2 r;
    asm("mov.b64 {%0, %1}, %2;" : "=f"(r.x), "=f"(r.y) : "l"(v));
    return r;
}

__device__ __forceinline__ float gelu_exact(float v) {
    return 0.5f * v * (1.0f + erff(v * 0.70710678118654752f));
}

// ---------------- fused GEMM: out = gelu(y @ M2^T + s*c + b) ----------------
#define GEMM_ROWS 64
#define WT_STRIDE 132
#define AT_STRIDE 66

__global__ void __launch_bounds__(256, 2)
gemm_fused_kernel(const float* __restrict__ A, const float* __restrict__ M2,
                  const float* __restrict__ cvec, const float* __restrict__ b,
                  const float* __restrict__ svec, float* __restrict__ C, int n) {
    extern __shared__ float smem[];
    float* Wt = smem;                          // [k][j], stride 132
    float* At = smem + HIDDEN * WT_STRIDE;     // [k][r], stride 66

    const int tid  = threadIdx.x;
    const int row0 = blockIdx.x * GEMM_ROWS;

    for (int i = tid; i < HIDDEN * HIDDEN; i += 256) {
        int j = i >> 7;
        int k = i & 127;
        Wt[k * WT_STRIDE + j] = M2[i];
    }
    const float4* A4 = reinterpret_cast<const float4*>(A);
    for (int i = tid; i < GEMM_ROWS * 32; i += 256) {
        int r  = i >> 5;
        int c4 = i & 31;
        int gr = row0 + r;
        float4 v = (gr < n) ? A4[(size_t)gr * 32 + c4] : make_float4(0.f, 0.f, 0.f, 0.f);
        At[(4 * c4 + 0) * AT_STRIDE + r] = v.x;
        At[(4 * c4 + 1) * AT_STRIDE + r] = v.y;
        At[(4 * c4 + 2) * AT_STRIDE + r] = v.z;
        At[(4 * c4 + 3) * AT_STRIDE + r] = v.w;
    }
    __syncthreads();

    const int tx = tid & 31;
    const int ty = tid >> 5;

    unsigned long long acc[4][4];
#pragma unroll
    for (int p = 0; p < 4; p++)
#pragma unroll
        for (int c = 0; c < 4; c++) acc[p][c] = 0ull;

    const float* at_base = &At[ty * 8];
    const float* wt_base = &Wt[tx * 4];

#pragma unroll 4
    for (int k = 0; k < HIDDEN; k++) {
        float4 w = *reinterpret_cast<const float4*>(&wt_base[k * WT_STRIDE]);
        unsigned long long w0 = f32x2_pack(w.x, w.x);
        unsigned long long w1 = f32x2_pack(w.y, w.y);
        unsigned long long w2 = f32x2_pack(w.z, w.z);
        unsigned long long w3 = f32x2_pack(w.w, w.w);
        const float* ak = &at_base[k * AT_STRIDE];
        unsigned long long a0 = *reinterpret_cast<const unsigned long long*>(ak + 0);
        unsigned long long a1 = *reinterpret_cast<const unsigned long long*>(ak + 2);
        unsigned long long a2 = *reinterpret_cast<const unsigned long long*>(ak + 4);
        unsigned long long a3 = *reinterpret_cast<const unsigned long long*>(ak + 6);
        f32x2_fma(acc[0][0], a0, w0); f32x2_fma(acc[0][1], a0, w1);
        f32x2_fma(acc[0][2], a0, w2); f32x2_fma(acc[0][3], a0, w3);
        f32x2_fma(acc[1][0], a1, w0); f32x2_fma(acc[1][1], a1, w1);
        f32x2_fma(acc[1][2], a1, w2); f32x2_fma(acc[1][3], a1, w3);
        f32x2_fma(acc[2][0], a2, w0); f32x2_fma(acc[2][1], a2, w1);
        f32x2_fma(acc[2][2], a2, w2); f32x2_fma(acc[2][3], a2, w3);
        f32x2_fma(acc[3][0], a3, w0); f32x2_fma(acc[3][1], a3, w1);
        f32x2_fma(acc[3][2], a3, w2); f32x2_fma(acc[3][3], a3, w3);
    }

    float4 bv = reinterpret_cast<const float4*>(b)[tx];
    float4 cv = reinterpret_cast<const float4*>(cvec)[tx];
#pragma unroll
    for (int p = 0; p < 4; p++) {
        int r0 = row0 + ty * 8 + 2 * p;
        float2 c0 = f32x2_unpack(acc[p][0]);
        float2 c1 = f32x2_unpack(acc[p][1]);
        float2 c2 = f32x2_unpack(acc[p][2]);
        float2 c3 = f32x2_unpack(acc[p][3]);
        float s0 = (r0 < n) ? svec[r0] : 0.f;
        float s1 = (r0 + 1 < n) ? svec[r0 + 1] : 0.f;
        float4 o0 = make_float4(c0.x + s0 * cv.x + bv.x, c1.x + s0 * cv.y + bv.y,
                                c2.x + s0 * cv.z + bv.z, c3.x + s0 * cv.w + bv.w);
        float4 o1 = make_float4(c0.y + s1 * cv.x + bv.x, c1.y + s1 * cv.y + bv.y,
                                c2.y + s1 * cv.z + bv.z, c3.y + s1 * cv.w + bv.w);
        o0.x = gelu_exact(o0.x); o0.y = gelu_exact(o0.y);
        o0.z = gelu_exact(o0.z); o0.w = gelu_exact(o0.w);
        o1.x = gelu_exact(o1.x); o1.y = gelu_exact(o1.y);
        o1.z = gelu_exact(o1.z); o1.w = gelu_exact(o1.w);
        if (r0 < n)
            *reinterpret_cast<float4*>(&C[(size_t)r0 * HIDDEN + tx * 4]) = o0;
        if (r0 + 1 < n)
            *reinterpret_cast<float4*>(&C[(size_t)(r0 + 1) * HIDDEN + tx * 4]) = o1;
    }
}

// ---------------- launch -----------------------------------------------------
extern "C" void kernel_launch(void* const* d_in, const int* in_sizes, int n_in,
                              void* d_out, int out_size) {
    const float* x = (const float*)d_in[0];
    const float* W = (const float*)d_in[1];
    const float* b = (const float*)d_in[2];
    const int* ei  = (const int*)d_in[3];

    const int n = in_sizes[0] / HIDDEN;   // 50000
    const int e = in_sizes[3] / 2;        // 800000
    const int* src = ei;
    const int* dst = ei + e;

    float* out = (float*)d_out;

    static float* p_y   = nullptr;
    static float* p_s   = nullptr;
    static float* p_M2  = nullptr;
    static float* p_c   = nullptr;
    static int*   p_deg = nullptr;
    static cudaStream_t s2 = nullptr;
    static cudaEvent_t ev_fork = nullptr, ev_join = nullptr;
    if (!p_y) {
        cudaGetSymbolAddress((void**)&p_y, g_y);
        cudaGetSymbolAddress((void**)&p_s, g_s);
        cudaGetSymbolAddress((void**)&p_M2, g_M2);
        cudaGetSymbolAddress((void**)&p_c, g_c);
        cudaGetSymbolAddress((void**)&p_deg, g_degi);
        cudaStreamCreateWithFlags(&s2, cudaStreamNonBlocking);
        cudaEventCreateWithFlags(&ev_fork, cudaEventDisableTiming);
        cudaEventCreateWithFlags(&ev_join, cudaEventDisableTiming);
    }

    const size_t smem_bytes = (HIDDEN * WT_STRIDE + HIDDEN * AT_STRIDE) * sizeof(float);
    cudaFuncSetAttribute(gemm_fused_kernel,
                         cudaFuncAttributeMaxDynamicSharedMemorySize, (int)smem_bytes);

    // ---- fork: x->fp16 convert + (M2, c) on side stream --------------------
    cudaEventRecord(ev_fork, 0);
    cudaStreamWaitEvent(s2, ev_fork, 0);
    int total4 = n * 32;  // float4 count
    cvt_kernel<<<(total4 + 255) / 256, 256, 0, s2>>>(x, total4);
    mat_kernel<<<17, 256, 0, s2>>>(W, b);
    cudaEventRecord(ev_join, s2);

    // ---- CSR build chain on main stream ------------------------------------
    cudaMemsetAsync(p_deg, 0, (size_t)n * sizeof(int));
    deg_kernel<<<(e + 255) / 256, 256>>>(dst, e);
    int nscan = (n + 1023) / 1024;  // 49 <= 64
    scan_block_kernel<<<nscan, 1024>>>(n);       // exclusive starts + deg^-1/2
    scan_sums_kernel<<<1, 64>>>(nscan);
    scan_add_kernel<<<(n + 255) / 256, 256>>>(n);
    fill_kernel<<<(e + 255) / 256, 256>>>(src, dst, e);

    // ---- join: gather needs fp16 x; fused GEMM needs M2, c ------------------
    cudaStreamWaitEvent(0, ev_join, 0);
    unsigned gthreads = (unsigned)n * 32u;
    gather_kernel<<<(gthreads + 255) / 256, 256>>>(n);

    const int gemm_blocks = (n + GEMM_ROWS - 1) / GEMM_ROWS;
    gemm_fused_kernel<<<gemm_blocks, 256, smem_bytes>>>(p_y, p_M2, p_c, b, p_s, out, n);
}

// round 7
// speedup vs baseline: 1.6797x; 1.0332x over previous
#include <cuda_runtime.h>
#include <cuda_fp16.h>
#include <math.h>

#define HIDDEN 128
#define MAXN 50000
#define MAXE 800000

// ---------------- scratch (device globals: no allocation allowed) ----------
__device__ float  g_y[(size_t)MAXN * HIDDEN];   // y = A·x  (gathered x)
__device__ __half g_xh[(size_t)MAXN * HIDDEN];  // fp16 copy of x
__device__ float  g_s[MAXN];                    // s[i] = sum of edge norms into i
__device__ int    g_degi[MAXN];                 // in-degree (int)
__device__ float  g_dinv[MAXN];                 // deg^-1/2
__device__ int    g_off[MAXN];                  // CSR starts; after fill = ends
__device__ int    g_edge[MAXE];                 // src per CSR slot (4B)
__device__ float  g_M2[HIDDEN * HIDDEN];        // M2 = W @ W
__device__ float  g_c[HIDDEN];                  // c  = W @ b
__device__ int    g_bsum[64];                   // block sums for scan

// ---------------- degree (int) ----------------------------------------------
__global__ void deg_kernel(const int* __restrict__ dst, int e) {
    int i = blockIdx.x * blockDim.x + threadIdx.x;
    if (i < e) atomicAdd(&g_degi[dst[i]], 1);
}

// ---------------- x -> fp16 (side stream) ------------------------------------
__global__ void __launch_bounds__(256)
cvt_kernel(const float* __restrict__ x, int total4) {
    int i = blockIdx.x * 256 + threadIdx.x;
    if (i < total4) {
        float4 v = reinterpret_cast<const float4*>(x)[i];
        __half2 a = __floats2half2_rn(v.x, v.y);
        __half2 b = __floats2half2_rn(v.z, v.w);
        uint2 o;
        o.x = *reinterpret_cast<unsigned*>(&a);
        o.y = *reinterpret_cast<unsigned*>(&b);
        reinterpret_cast<uint2*>(g_xh)[i] = o;
    }
}

// ---------------- 3-kernel scan -> exclusive starts (+ fused deg^-1/2) -------
__global__ void __launch_bounds__(1024)
scan_block_kernel(int n) {
    __shared__ int sh[1024];
    int t = threadIdx.x;
    int i = blockIdx.x * 1024 + t;
    int v = (i < n) ? g_degi[i] : 0;
    if (i < n) g_dinv[i] = rsqrtf((float)v);
    sh[t] = v;
    __syncthreads();
    for (int d = 1; d < 1024; d <<= 1) {
        int u = (t >= d) ? sh[t - d] : 0;
        __syncthreads();
        sh[t] += u;
        __syncthreads();
    }
    if (i < n) g_off[i] = sh[t] - v;           // exclusive within block
    if (t == 1023) g_bsum[blockIdx.x] = sh[1023];
}

__global__ void scan_sums_kernel(int nb) {
    __shared__ int sh[64];
    int t = threadIdx.x;
    sh[t] = (t < nb) ? g_bsum[t] : 0;
    __syncthreads();
    for (int d = 1; d < 64; d <<= 1) {
        int u = (t >= d) ? sh[t - d] : 0;
        __syncthreads();
        sh[t] += u;
        __syncthreads();
    }
    if (t < nb) g_bsum[t] = sh[t];             // inclusive block prefix
}

__global__ void scan_add_kernel(int n) {
    int i = blockIdx.x * blockDim.x + threadIdx.x;
    if (i < n) {
        int blk = i >> 10;
        if (blk > 0) g_off[i] += g_bsum[blk - 1];
    }
}

// ---------------- CSR fill: cursor-free, 4B record (src only) ---------------
__global__ void fill_kernel(const int* __restrict__ src, const int* __restrict__ dst, int e) {
    int i = blockIdx.x * blockDim.x + threadIdx.x;
    if (i < e) {
        int s = src[i];
        int d = dst[i];
        int pos = atomicAdd(&g_off[d], 1);
        g_edge[pos] = s;
    }
}

// ---------------- M2 = W @ W and c = W @ b (tiny, side stream) ---------------
__global__ void __launch_bounds__(256)
mat_kernel(const float* __restrict__ W, const float* __restrict__ b) {
    if (blockIdx.x == 16) {
        int j = threadIdx.x;
        if (j < HIDDEN) {
            float acc = 0.f;
            for (int k = 0; k < HIDDEN; k++) acc += W[j * HIDDEN + k] * b[k];
            g_c[j] = acc;
        }
        return;
    }
    __shared__ float Wsh[8][HIDDEN];
    const int jbase = blockIdx.x * 8;
    const int tid = threadIdx.x;
    for (int i = tid; i < 8 * HIDDEN; i += 256)
        Wsh[i >> 7][i & 127] = W[(jbase + (i >> 7)) * HIDDEN + (i & 127)];
    __syncthreads();
    const int m = tid & 127;
    const int half = tid >> 7;
    float acc[4] = {0.f, 0.f, 0.f, 0.f};
    for (int k = 0; k < HIDDEN; k++) {
        float wk = __ldg(&W[k * HIDDEN + m]);
#pragma unroll
        for (int q = 0; q < 4; q++) acc[q] += Wsh[half * 4 + q][k] * wk;
    }
#pragma unroll
    for (int q = 0; q < 4; q++)
        g_M2[(jbase + half * 4 + q) * HIDDEN + m] = acc[q];
}

// ---------------- gather: y[i]=dinv[i]*sum dinv[s]*x16[s]; s[i]=dinv[i]*sum --
// One warp per dst node; lane owns 4 columns. Edge record is 4B; dinv[s] is a
// warp-uniform broadcast load from a 200KB L2-hot array.
__global__ void __launch_bounds__(256)
gather_kernel(int n) {
    int warp = (blockIdx.x * 256 + threadIdx.x) >> 5;
    int lane = threadIdx.x & 31;
    if (warp >= n) return;
    // after fill: g_off[i] = end of row i; start = end of row i-1 (0 for i=0)
    int p  = (warp == 0) ? 0 : __ldg(&g_off[warp - 1]);
    int pe = __ldg(&g_off[warp]);
    const uint2* x2 = reinterpret_cast<const uint2*>(g_xh);
    float4 acc = make_float4(0.f, 0.f, 0.f, 0.f);
    float wsum = 0.f;
#pragma unroll 1
    for (; p + 3 < pe; p += 4) {
        int s0 = __ldg(&g_edge[p]);
        int s1 = __ldg(&g_edge[p + 1]);
        int s2 = __ldg(&g_edge[p + 2]);
        int s3 = __ldg(&g_edge[p + 3]);
        float w0 = __ldg(&g_dinv[s0]);
        float w1 = __ldg(&g_dinv[s1]);
        float w2 = __ldg(&g_dinv[s2]);
        float w3 = __ldg(&g_dinv[s3]);
        uint2 u0 = __ldg(&x2[(size_t)s0 * 32 + lane]);
        uint2 u1 = __ldg(&x2[(size_t)s1 * 32 + lane]);
        uint2 u2 = __ldg(&x2[(size_t)s2 * 32 + lane]);
        uint2 u3 = __ldg(&x2[(size_t)s3 * 32 + lane]);
        wsum += w0 + w1 + w2 + w3;
        float2 a0 = __half22float2(*reinterpret_cast<__half2*>(&u0.x));
        float2 b0 = __half22float2(*reinterpret_cast<__half2*>(&u0.y));
        float2 a1 = __half22float2(*reinterpret_cast<__half2*>(&u1.x));
        float2 b1 = __half22float2(*reinterpret_cast<__half2*>(&u1.y));
        float2 a2 = __half22float2(*reinterpret_cast<__half2*>(&u2.x));
        float2 b2 = __half22float2(*reinterpret_cast<__half2*>(&u2.y));
        float2 a3 = __half22float2(*reinterpret_cast<__half2*>(&u3.x));
        float2 b3 = __half22float2(*reinterpret_cast<__half2*>(&u3.y));
        acc.x += w0 * a0.x + w1 * a1.x + w2 * a2.x + w3 * a3.x;
        acc.y += w0 * a0.y + w1 * a1.y + w2 * a2.y + w3 * a3.y;
        acc.z += w0 * b0.x + w1 * b1.x + w2 * b2.x + w3 * b3.x;
        acc.w += w0 * b0.y + w1 * b1.y + w2 * b2.y + w3 * b3.y;
    }
    for (; p < pe; p++) {
        int s0 = __ldg(&g_edge[p]);
        float w0 = __ldg(&g_dinv[s0]);
        uint2 u0 = __ldg(&x2[(size_t)s0 * 32 + lane]);
        wsum += w0;
        float2 a0 = __half22float2(*reinterpret_cast<__half2*>(&u0.x));
        float2 b0 = __half22float2(*reinterpret_cast<__half2*>(&u0.y));
        acc.x += w0 * a0.x; acc.y += w0 * a0.y;
        acc.z += w0 * b0.x; acc.w += w0 * b0.y;
    }
    float di = g_dinv[warp];
    acc.x *= di; acc.y *= di; acc.z *= di; acc.w *= di;
    reinterpret_cast<float4*>(g_y)[(size_t)warp * 32 + lane] = acc;
    if (lane == 0) g_s[warp] = wsum * di;
}

// ---------------- packed f32x2 helpers ---------------------------------------
__device__ __forceinline__ unsigned long long f32x2_pack(float lo, float hi) {
    unsigned long long r;
    asm("mov.b64 %0, {%1, %2};" : "=l"(r) : "f"(lo), "f"(hi));
    return r;
}
__device__ __forceinline__ void f32x2_fma(unsigned long long& d,
                                          unsigned long long a, unsigned long long b) {
    asm("fma.rn.f32x2 %0, %1, %2, %0;" : "+l"(d) : "l"(a), "l"(b));
}
__device__ __forceinline__ float2 f32x2_unpack(unsigned long long v) {
    float2 r;
    asm("mov.b64 {%0, %1}, %2;" : "=f"(r.x), "=f"(r.y) : "l"(v));
    return r;
}

__device__ __forceinline__ float gelu_exact(float v) {
    return 0.5f * v * (1.0f + erff(v * 0.70710678118654752f));
}

// ---------------- fused GEMM: out = gelu(y @ M2^T + s*c + b) ----------------
#define GEMM_ROWS 64
#define WT_STRIDE 132
#define AT_STRIDE 66

__global__ void __launch_bounds__(256, 2)
gemm_fused_kernel(const float* __restrict__ A, const float* __restrict__ M2,
                  const float* __restrict__ cvec, const float* __restrict__ b,
                  const float* __restrict__ svec, float* __restrict__ C, int n) {
    extern __shared__ float smem[];
    float* Wt = smem;                          // [k][j], stride 132
    float* At = smem + HIDDEN * WT_STRIDE;     // [k][r], stride 66

    const int tid  = threadIdx.x;
    const int row0 = blockIdx.x * GEMM_ROWS;

    for (int i = tid; i < HIDDEN * HIDDEN; i += 256) {
        int j = i >> 7;
        int k = i & 127;
        Wt[k * WT_STRIDE + j] = M2[i];
    }
    const float4* A4 = reinterpret_cast<const float4*>(A);
    for (int i = tid; i < GEMM_ROWS * 32; i += 256) {
        int r  = i >> 5;
        int c4 = i & 31;
        int gr = row0 + r;
        float4 v = (gr < n) ? A4[(size_t)gr * 32 + c4] : make_float4(0.f, 0.f, 0.f, 0.f);
        At[(4 * c4 + 0) * AT_STRIDE + r] = v.x;
        At[(4 * c4 + 1) * AT_STRIDE + r] = v.y;
        At[(4 * c4 + 2) * AT_STRIDE + r] = v.z;
        At[(4 * c4 + 3) * AT_STRIDE + r] = v.w;
    }
    __syncthreads();

    const int tx = tid & 31;
    const int ty = tid >> 5;

    unsigned long long acc[4][4];
#pragma unroll
    for (int p = 0; p < 4; p++)
#pragma unroll
        for (int c = 0; c < 4; c++) acc[p][c] = 0ull;

    const float* at_base = &At[ty * 8];
    const float* wt_base = &Wt[tx * 4];

#pragma unroll 4
    for (int k = 0; k < HIDDEN; k++) {
        float4 w = *reinterpret_cast<const float4*>(&wt_base[k * WT_STRIDE]);
        unsigned long long w0 = f32x2_pack(w.x, w.x);
        unsigned long long w1 = f32x2_pack(w.y, w.y);
        unsigned long long w2 = f32x2_pack(w.z, w.z);
        unsigned long long w3 = f32x2_pack(w.w, w.w);
        const float* ak = &at_base[k * AT_STRIDE];
        unsigned long long a0 = *reinterpret_cast<const unsigned long long*>(ak + 0);
        unsigned long long a1 = *reinterpret_cast<const unsigned long long*>(ak + 2);
        unsigned long long a2 = *reinterpret_cast<const unsigned long long*>(ak + 4);
        unsigned long long a3 = *reinterpret_cast<const unsigned long long*>(ak + 6);
        f32x2_fma(acc[0][0], a0, w0); f32x2_fma(acc[0][1], a0, w1);
        f32x2_fma(acc[0][2], a0, w2); f32x2_fma(acc[0][3], a0, w3);
        f32x2_fma(acc[1][0], a1, w0); f32x2_fma(acc[1][1], a1, w1);
        f32x2_fma(acc[1][2], a1, w2); f32x2_fma(acc[1][3], a1, w3);
        f32x2_fma(acc[2][0], a2, w0); f32x2_fma(acc[2][1], a2, w1);
        f32x2_fma(acc[2][2], a2, w2); f32x2_fma(acc[2][3], a2, w3);
        f32x2_fma(acc[3][0], a3, w0); f32x2_fma(acc[3][1], a3, w1);
        f32x2_fma(acc[3][2], a3, w2); f32x2_fma(acc[3][3], a3, w3);
    }

    float4 bv = reinterpret_cast<const float4*>(b)[tx];
    float4 cv = reinterpret_cast<const float4*>(cvec)[tx];
#pragma unroll
    for (int p = 0; p < 4; p++) {
        int r0 = row0 + ty * 8 + 2 * p;
        float2 c0 = f32x2_unpack(acc[p][0]);
        float2 c1 = f32x2_unpack(acc[p][1]);
        float2 c2 = f32x2_unpack(acc[p][2]);
        float2 c3 = f32x2_unpack(acc[p][3]);
        float s0 = (r0 < n) ? svec[r0] : 0.f;
        float s1 = (r0 + 1 < n) ? svec[r0 + 1] : 0.f;
        float4 o0 = make_float4(c0.x + s0 * cv.x + bv.x, c1.x + s0 * cv.y + bv.y,
                                c2.x + s0 * cv.z + bv.z, c3.x + s0 * cv.w + bv.w);
        float4 o1 = make_float4(c0.y + s1 * cv.x + bv.x, c1.y + s1 * cv.y + bv.y,
                                c2.y + s1 * cv.z + bv.z, c3.y + s1 * cv.w + bv.w);
        o0.x = gelu_exact(o0.x); o0.y = gelu_exact(o0.y);
        o0.z = gelu_exact(o0.z); o0.w = gelu_exact(o0.w);
        o1.x = gelu_exact(o1.x); o1.y = gelu_exact(o1.y);
        o1.z = gelu_exact(o1.z); o1.w = gelu_exact(o1.w);
        if (r0 < n)
            *reinterpret_cast<float4*>(&C[(size_t)r0 * HIDDEN + tx * 4]) = o0;
        if (r0 + 1 < n)
            *reinterpret_cast<float4*>(&C[(size_t)(r0 + 1) * HIDDEN + tx * 4]) = o1;
    }
}

// ---------------- launch -----------------------------------------------------
extern "C" void kernel_launch(void* const* d_in, const int* in_sizes, int n_in,
                              void* d_out, int out_size) {
    const float* x = (const float*)d_in[0];
    const float* W = (const float*)d_in[1];
    const float* b = (const float*)d_in[2];
    const int* ei  = (const int*)d_in[3];

    const int n = in_sizes[0] / HIDDEN;   // 50000
    const int e = in_sizes[3] / 2;        // 800000
    const int* src = ei;
    const int* dst = ei + e;

    float* out = (float*)d_out;

    static float* p_y   = nullptr;
    static float* p_s   = nullptr;
    static float* p_M2  = nullptr;
    static float* p_c   = nullptr;
    static int*   p_deg = nullptr;
    static cudaStream_t s2 = nullptr;
    static cudaEvent_t ev_fork = nullptr, ev_join = nullptr;
    if (!p_y) {
        cudaGetSymbolAddress((void**)&p_y, g_y);
        cudaGetSymbolAddress((void**)&p_s, g_s);
        cudaGetSymbolAddress((void**)&p_M2, g_M2);
        cudaGetSymbolAddress((void**)&p_c, g_c);
        cudaGetSymbolAddress((void**)&p_deg, g_degi);
        cudaStreamCreateWithFlags(&s2, cudaStreamNonBlocking);
        cudaEventCreateWithFlags(&ev_fork, cudaEventDisableTiming);
        cudaEventCreateWithFlags(&ev_join, cudaEventDisableTiming);
    }

    const size_t smem_bytes = (HIDDEN * WT_STRIDE + HIDDEN * AT_STRIDE) * sizeof(float);
    cudaFuncSetAttribute(gemm_fused_kernel,
                         cudaFuncAttributeMaxDynamicSharedMemorySize, (int)smem_bytes);

    // ---- fork: x->fp16 convert + (M2, c) on side stream --------------------
    cudaEventRecord(ev_fork, 0);
    cudaStreamWaitEvent(s2, ev_fork, 0);
    int total4 = n * 32;  // float4 count
    cvt_kernel<<<(total4 + 255) / 256, 256, 0, s2>>>(x, total4);
    mat_kernel<<<17, 256, 0, s2>>>(W, b);
    cudaEventRecord(ev_join, s2);

    // ---- CSR build chain on main stream ------------------------------------
    cudaMemsetAsync(p_deg, 0, (size_t)n * sizeof(int));
    deg_kernel<<<(e + 255) / 256, 256>>>(dst, e);
    int nscan = (n + 1023) / 1024;  // 49 <= 64
    scan_block_kernel<<<nscan, 1024>>>(n);       // exclusive starts + deg^-1/2
    scan_sums_kernel<<<1, 64>>>(nscan);
    scan_add_kernel<<<(n + 255) / 256, 256>>>(n);
    fill_kernel<<<(e + 255) / 256, 256>>>(src, dst, e);

    // ---- join: gather needs fp16 x; fused GEMM needs M2, c ------------------
    cudaStreamWaitEvent(0, ev_join, 0);
    unsigned gthreads = (unsigned)n * 32u;
    gather_kernel<<<(gthreads + 255) / 256, 256>>>(n);

    const int gemm_blocks = (n + GEMM_ROWS - 1) / GEMM_ROWS;
    gemm_fused_kernel<<<gemm_blocks, 256, smem_bytes>>>(p_y, p_M2, p_c, b, p_s, out, n);
}

// round 9
// speedup vs baseline: 1.8208x; 1.0840x over previous
#include <cuda_runtime.h>
#include <cuda_fp16.h>
#include <math.h>

#define HIDDEN 128
#define MAXN 50000
#define MAXE 800000

// ---------------- scratch (device globals: no allocation allowed) ----------
__device__ __half g_zh[(size_t)MAXN * HIDDEN];  // z = x @ M2^T in fp16
__device__ int    g_degi[MAXN];                 // in-degree (int)
__device__ float  g_dinv[MAXN];                 // deg^-1/2
__device__ int    g_off[MAXN];                  // CSR starts; after fill = ends
__device__ int    g_edge[MAXE];                 // src per CSR slot (4B)
__device__ float  g_M2[HIDDEN * HIDDEN];        // M2 = W @ W (fp32)
__device__ float  g_c[HIDDEN];                  // c  = W @ b
__device__ int    g_bsum[64];                   // block sums for scan

// ---------------- degree (int) ----------------------------------------------
__global__ void deg_kernel(const int* __restrict__ dst, int e) {
    int i = blockIdx.x * blockDim.x + threadIdx.x;
    if (i < e) atomicAdd(&g_degi[dst[i]], 1);
}

// ---------------- 2-kernel scan -> exclusive starts (+ fused deg^-1/2) -------
__global__ void __launch_bounds__(1024)
scan_block_kernel(int n) {
    __shared__ int sh[1024];
    int t = threadIdx.x;
    int i = blockIdx.x * 1024 + t;
    int v = (i < n) ? g_degi[i] : 0;
    if (i < n) g_dinv[i] = rsqrtf((float)v);
    sh[t] = v;
    __syncthreads();
    for (int d = 1; d < 1024; d <<= 1) {
        int u = (t >= d) ? sh[t - d] : 0;
        __syncthreads();
        sh[t] += u;
        __syncthreads();
    }
    if (i < n) g_off[i] = sh[t] - v;           // exclusive within block
    if (t == 1023) g_bsum[blockIdx.x] = sh[1023];
}

__global__ void __launch_bounds__(1024)
scan_add_kernel(int n) {
    __shared__ int pre;
    int blk = blockIdx.x;
    if (threadIdx.x == 0) {
        int s = 0;
        for (int i = 0; i < blk; i++) s += g_bsum[i];
        pre = s;
    }
    __syncthreads();
    int i = blk * 1024 + threadIdx.x;
    if (i < n && blk > 0) g_off[i] += pre;
}

// ---------------- CSR fill: cursor-free, 4B record (src only) ---------------
__global__ void fill_kernel(const int* __restrict__ src, const int* __restrict__ dst, int e) {
    int i = blockIdx.x * blockDim.x + threadIdx.x;
    if (i < e) {
        int s = src[i];
        int d = dst[i];
        int pos = atomicAdd(&g_off[d], 1);
        g_edge[pos] = s;
    }
}

// ---------------- M2 = W @ W and c = W @ b (tiny, side stream) ---------------
__global__ void __launch_bounds__(256)
mat_kernel(const float* __restrict__ W, const float* __restrict__ b) {
    if (blockIdx.x == 16) {
        int j = threadIdx.x;
        if (j < HIDDEN) {
            float acc = 0.f;
            for (int k = 0; k < HIDDEN; k++) acc += W[j * HIDDEN + k] * b[k];
            g_c[j] = acc;
        }
        return;
    }
    __shared__ float Wsh[8][HIDDEN];
    const int jbase = blockIdx.x * 8;
    const int tid = threadIdx.x;
    for (int i = tid; i < 8 * HIDDEN; i += 256)
        Wsh[i >> 7][i & 127] = W[(jbase + (i >> 7)) * HIDDEN + (i & 127)];
    __syncthreads();
    const int m = tid & 127;
    const int half = tid >> 7;
    float acc[4] = {0.f, 0.f, 0.f, 0.f};
    for (int k = 0; k < HIDDEN; k++) {
        float wk = __ldg(&W[k * HIDDEN + m]);
#pragma unroll
        for (int q = 0; q < 4; q++) acc[q] += Wsh[half * 4 + q][k] * wk;
    }
#pragma unroll
    for (int q = 0; q < 4; q++)
        g_M2[(jbase + half * 4 + q) * HIDDEN + m] = acc[q];
}

// ---------------- packed f32x2 helpers ---------------------------------------
__device__ __forceinline__ unsigned long long f32x2_pack(float lo, float hi) {
    unsigned long long r;
    asm("mov.b64 %0, {%1, %2};" : "=l"(r) : "f"(lo), "f"(hi));
    return r;
}
__device__ __forceinline__ void f32x2_fma(unsigned long long& d,
                                          unsigned long long a, unsigned long long b) {
    asm("fma.rn.f32x2 %0, %1, %2, %0;" : "+l"(d) : "l"(a), "l"(b));
}
__device__ __forceinline__ float2 f32x2_unpack(unsigned long long v) {
    float2 r;
    asm("mov.b64 {%0, %1}, %2;" : "=f"(r.x), "=f"(r.y) : "l"(v));
    return r;
}

__device__ __forceinline__ float gelu_exact(float v) {
    return 0.5f * v * (1.0f + erff(v * 0.70710678118654752f));
}

// ---------------- GEMM (side stream): z = x @ M2^T, fp16 output --------------
// FFMA2: x tile k-major (row pairs load as packed b64), M2 col-padded.
// Thread tile 8 rows (4 packed pairs) x 4 cols. Output converted to fp16.
#define GEMM_ROWS 64
#define WT_STRIDE 132
#define AT_STRIDE 66

__global__ void __launch_bounds__(256, 2)
gemmz_kernel(const float* __restrict__ A, const float* __restrict__ M2, int n) {
    extern __shared__ float smem[];
    float* Wt = smem;                          // [k][j], stride 132
    float* At = smem + HIDDEN * WT_STRIDE;     // [k][r], stride 66

    const int tid  = threadIdx.x;
    const int row0 = blockIdx.x * GEMM_ROWS;

    for (int i = tid; i < HIDDEN * HIDDEN; i += 256) {
        int j = i >> 7;
        int k = i & 127;
        Wt[k * WT_STRIDE + j] = M2[i];
    }
    const float4* A4 = reinterpret_cast<const float4*>(A);
    for (int i = tid; i < GEMM_ROWS * 32; i += 256) {
        int r  = i >> 5;
        int c4 = i & 31;
        int gr = row0 + r;
        float4 v = (gr < n) ? A4[(size_t)gr * 32 + c4] : make_float4(0.f, 0.f, 0.f, 0.f);
        At[(4 * c4 + 0) * AT_STRIDE + r] = v.x;
        At[(4 * c4 + 1) * AT_STRIDE + r] = v.y;
        At[(4 * c4 + 2) * AT_STRIDE + r] = v.z;
        At[(4 * c4 + 3) * AT_STRIDE + r] = v.w;
    }
    __syncthreads();

    const int tx = tid & 31;
    const int ty = tid >> 5;

    unsigned long long acc[4][4];
#pragma unroll
    for (int p = 0; p < 4; p++)
#pragma unroll
        for (int c = 0; c < 4; c++) acc[p][c] = 0ull;

    const float* at_base = &At[ty * 8];
    const float* wt_base = &Wt[tx * 4];

#pragma unroll 4
    for (int k = 0; k < HIDDEN; k++) {
        float4 w = *reinterpret_cast<const float4*>(&wt_base[k * WT_STRIDE]);
        unsigned long long w0 = f32x2_pack(w.x, w.x);
        unsigned long long w1 = f32x2_pack(w.y, w.y);
        unsigned long long w2 = f32x2_pack(w.z, w.z);
        unsigned long long w3 = f32x2_pack(w.w, w.w);
        const float* ak = &at_base[k * AT_STRIDE];
        unsigned long long a0 = *reinterpret_cast<const unsigned long long*>(ak + 0);
        unsigned long long a1 = *reinterpret_cast<const unsigned long long*>(ak + 2);
        unsigned long long a2 = *reinterpret_cast<const unsigned long long*>(ak + 4);
        unsigned long long a3 = *reinterpret_cast<const unsigned long long*>(ak + 6);
        f32x2_fma(acc[0][0], a0, w0); f32x2_fma(acc[0][1], a0, w1);
        f32x2_fma(acc[0][2], a0, w2); f32x2_fma(acc[0][3], a0, w3);
        f32x2_fma(acc[1][0], a1, w0); f32x2_fma(acc[1][1], a1, w1);
        f32x2_fma(acc[1][2], a1, w2); f32x2_fma(acc[1][3], a1, w3);
        f32x2_fma(acc[2][0], a2, w0); f32x2_fma(acc[2][1], a2, w1);
        f32x2_fma(acc[2][2], a2, w2); f32x2_fma(acc[2][3], a2, w3);
        f32x2_fma(acc[3][0], a3, w0); f32x2_fma(acc[3][1], a3, w1);
        f32x2_fma(acc[3][2], a3, w2); f32x2_fma(acc[3][3], a3, w3);
    }

    uint2* zh2 = reinterpret_cast<uint2*>(g_zh);
#pragma unroll
    for (int p = 0; p < 4; p++) {
        int r0 = row0 + ty * 8 + 2 * p;
        float2 c0 = f32x2_unpack(acc[p][0]);
        float2 c1 = f32x2_unpack(acc[p][1]);
        float2 c2 = f32x2_unpack(acc[p][2]);
        float2 c3 = f32x2_unpack(acc[p][3]);
        if (r0 < n) {
            __half2 h01 = __floats2half2_rn(c0.x, c1.x);
            __half2 h23 = __floats2half2_rn(c2.x, c3.x);
            uint2 u;
            u.x = *reinterpret_cast<unsigned*>(&h01);
            u.y = *reinterpret_cast<unsigned*>(&h23);
            zh2[(size_t)r0 * 32 + tx] = u;
        }
        if (r0 + 1 < n) {
            __half2 h01 = __floats2half2_rn(c0.y, c1.y);
            __half2 h23 = __floats2half2_rn(c2.y, c3.y);
            uint2 u;
            u.x = *reinterpret_cast<unsigned*>(&h01);
            u.y = *reinterpret_cast<unsigned*>(&h23);
            zh2[(size_t)(r0 + 1) * 32 + tx] = u;
        }
    }
}

// ---------------- final: out[i] = gelu(dinv_i * sum dinv_s * z[s] + s_i*c + b)
// One warp per dst node; lane owns 4 columns. Writes d_out directly.
__global__ void __launch_bounds__(256)
gather_out_kernel(const float* __restrict__ cvec, const float* __restrict__ bvec,
                  float* __restrict__ out, int n) {
    int warp = (blockIdx.x * 256 + threadIdx.x) >> 5;
    int lane = threadIdx.x & 31;
    if (warp >= n) return;
    // after fill: g_off[i] = end of row i; start = end of row i-1 (0 for i=0)
    int p  = (warp == 0) ? 0 : __ldg(&g_off[warp - 1]);
    int pe = __ldg(&g_off[warp]);
    const uint2* z2 = reinterpret_cast<const uint2*>(g_zh);
    float4 acc = make_float4(0.f, 0.f, 0.f, 0.f);
    float wsum = 0.f;
#pragma unroll 1
    for (; p + 3 < pe; p += 4) {
        int s0 = __ldg(&g_edge[p]);
        int s1 = __ldg(&g_edge[p + 1]);
        int s2 = __ldg(&g_edge[p + 2]);
        int s3 = __ldg(&g_edge[p + 3]);
        float w0 = __ldg(&g_dinv[s0]);
        float w1 = __ldg(&g_dinv[s1]);
        float w2 = __ldg(&g_dinv[s2]);
        float w3 = __ldg(&g_dinv[s3]);
        uint2 u0 = __ldg(&z2[(size_t)s0 * 32 + lane]);
        uint2 u1 = __ldg(&z2[(size_t)s1 * 32 + lane]);
        uint2 u2 = __ldg(&z2[(size_t)s2 * 32 + lane]);
        uint2 u3 = __ldg(&z2[(size_t)s3 * 32 + lane]);
        wsum += w0 + w1 + w2 + w3;
        float2 a0 = __half22float2(*reinterpret_cast<__half2*>(&u0.x));
        float2 b0 = __half22float2(*reinterpret_cast<__half2*>(&u0.y));
        float2 a1 = __half22float2(*reinterpret_cast<__half2*>(&u1.x));
        float2 b1 = __half22float2(*reinterpret_cast<__half2*>(&u1.y));
        float2 a2 = __half22float2(*reinterpret_cast<__half2*>(&u2.x));
        float2 b2 = __half22float2(*reinterpret_cast<__half2*>(&u2.y));
        float2 a3 = __half22float2(*reinterpret_cast<__half2*>(&u3.x));
        float2 b3 = __half22float2(*reinterpret_cast<__half2*>(&u3.y));
        acc.x += w0 * a0.x + w1 * a1.x + w2 * a2.x + w3 * a3.x;
        acc.y += w0 * a0.y + w1 * a1.y + w2 * a2.y + w3 * a3.y;
        acc.z += w0 * b0.x + w1 * b1.x + w2 * b2.x + w3 * b3.x;
        acc.w += w0 * b0.y + w1 * b1.y + w2 * b2.y + w3 * b3.y;
    }
    for (; p < pe; p++) {
        int s0 = __ldg(&g_edge[p]);
        float w0 = __ldg(&g_dinv[s0]);
        uint2 u0 = __ldg(&z2[(size_t)s0 * 32 + lane]);
        wsum += w0;
        float2 a0 = __half22float2(*reinterpret_cast<__half2*>(&u0.x));
        float2 b0 = __half22float2(*reinterpret_cast<__half2*>(&u0.y));
        acc.x += w0 * a0.x; acc.y += w0 * a0.y;
        acc.z += w0 * b0.x; acc.w += w0 * b0.y;
    }
    float di = __ldg(&g_dinv[warp]);
    float sc = di * wsum;                       // s_i
    float4 cv = reinterpret_cast<const float4*>(cvec)[lane];
    float4 bv = reinterpret_cast<const float4*>(bvec)[lane];
    float4 o;
    o.x = gelu_exact(di * acc.x + sc * cv.x + bv.x);
    o.y = gelu_exact(di * acc.y + sc * cv.y + bv.y);
    o.z = gelu_exact(di * acc.z + sc * cv.z + bv.z);
    o.w = gelu_exact(di * acc.w + sc * cv.w + bv.w);
    reinterpret_cast<float4*>(out)[(size_t)warp * 32 + lane] = o;
}

// ---------------- launch -----------------------------------------------------
extern "C" void kernel_launch(void* const* d_in, const int* in_sizes, int n_in,
                              void* d_out, int out_size) {
    const float* x = (const float*)d_in[0];
    const float* W = (const float*)d_in[1];
    const float* b = (const float*)d_in[2];
    const int* ei  = (const int*)d_in[3];

    const int n = in_sizes[0] / HIDDEN;   // 50000
    const int e = in_sizes[3] / 2;        // 800000
    const int* src = ei;
    const int* dst = ei + e;

    float* out = (float*)d_out;

    static float* p_M2  = nullptr;
    static float* p_c   = nullptr;
    static int*   p_deg = nullptr;
    static cudaStream_t s2 = nullptr;
    static cudaEvent_t ev_fork = nullptr, ev_join = nullptr;
    if (!p_M2) {
        cudaGetSymbolAddress((void**)&p_M2, g_M2);
        cudaGetSymbolAddress((void**)&p_c, g_c);
        cudaGetSymbolAddress((void**)&p_deg, g_degi);
        cudaStreamCreateWithFlags(&s2, cudaStreamNonBlocking);
        cudaEventCreateWithFlags(&ev_fork, cudaEventDisableTiming);
        cudaEventCreateWithFlags(&ev_join, cudaEventDisableTiming);
        const size_t smem_bytes = (HIDDEN * WT_STRIDE + HIDDEN * AT_STRIDE) * sizeof(float);
        cudaFuncSetAttribute(gemmz_kernel,
                             cudaFuncAttributeMaxDynamicSharedMemorySize, (int)smem_bytes);
    }
    const size_t smem_bytes = (HIDDEN * WT_STRIDE + HIDDEN * AT_STRIDE) * sizeof(float);

    // ---- fork: M2/c then z = x @ M2^T (fp16) on side stream ----------------
    cudaEventRecord(ev_fork, 0);
    cudaStreamWaitEvent(s2, ev_fork, 0);
    mat_kernel<<<17, 256, 0, s2>>>(W, b);
    const int gemm_blocks = (n + GEMM_ROWS - 1) / GEMM_ROWS;
    gemmz_kernel<<<gemm_blocks, 256, smem_bytes, s2>>>(x, p_M2, n);
    cudaEventRecord(ev_join, s2);

    // ---- CSR build chain on main stream (concurrent with GEMM) --------------
    cudaMemsetAsync(p_deg, 0, (size_t)n * sizeof(int));
    deg_kernel<<<(e + 255) / 256, 256>>>(dst, e);
    int nscan = (n + 1023) / 1024;  // 49
    scan_block_kernel<<<nscan, 1024>>>(n);
    scan_add_kernel<<<nscan, 1024>>>(n);
    fill_kernel<<<(e + 255) / 256, 256>>>(src, dst, e);

    // ---- join: final gather+epilogue needs z, CSR, c ------------------------
    cudaStreamWaitEvent(0, ev_join, 0);
    unsigned gthreads = (unsigned)n * 32u;
    gather_out_kernel<<<(gthreads + 255) / 256, 256>>>(p_c, b, out, n);
}